// round 7
// baseline (speedup 1.0000x reference)
#include <cuda_runtime.h>
#include <cuda_bf16.h>
#include <cstdint>

#define NB 256
#define NS 2048
#define NK 64
#define LN2F 0.69314718055994531f
#define NBLK 640

// Scratch (device globals — no allocation allowed)
__device__ float g_vecA[NB][NK];
__device__ float g_vecB[NB][NK];
__device__ float g_offA[NB];
__device__ float g_offB[NB];
__device__ float g_gold[NB];
__device__ unsigned g_done;   // zero-init; reset by last block each launch

typedef __nv_bfloat162 bf2;

__device__ __forceinline__ bf2 u2b(unsigned u) { return *reinterpret_cast<bf2*>(&u); }
__device__ __forceinline__ unsigned b2u(bf2 v) { return *reinterpret_cast<unsigned*>(&v); }

struct __align__(128) ChainSmem {
    bf2  sA[2][NK];   // copy A (512 B), double buffered
    char pad[16];     // bank-shift copy B by 4 banks vs copy A
    bf2  sB[2][NK];   // copy B (512 B)
    float slot[2];    // per-warp published max
    float red[2];     // final reduction
    int  last;
};

// half matvec: lane sums its 32-i half for its output pair.
// 8x LDS.128 (2 distinct addrs/instr, disjoint banks) + 32x HFMA2.
__device__ __forceinline__ bf2 mvh(const uint4* __restrict__ q, const unsigned (&Er)[32]) {
    bf2 z = __floats2bfloat162_rn(0.f, 0.f);
    bf2 c0 = z, c1 = z, c2 = z, c3 = z;
    #pragma unroll
    for (int g = 0; g < 8; g++) {
        uint4 v = q[g];
        c0 = __hfma2(u2b(v.x), u2b(Er[4 * g + 0]), c0);
        c1 = __hfma2(u2b(v.y), u2b(Er[4 * g + 1]), c1);
        c2 = __hfma2(u2b(v.z), u2b(Er[4 * g + 2]), c2);
        c3 = __hfma2(u2b(v.w), u2b(Er[4 * g + 3]), c3);
    }
    return __hadd2(__hadd2(c0, c1), __hadd2(c2, c3));
}

// Store (v.lo,v.lo),(v.hi,v.hi) as one STS.64.
__device__ __forceinline__ void store_dup(uint2* dst, bf2 v) {
    unsigned u = b2u(v);
    uint2 d;
    d.x = __byte_perm(u, u, 0x1010);
    d.y = __byte_perm(u, u, 0x3232);
    *dst = d;
}

__device__ __forceinline__ float warp_fmax(float m) {
    #pragma unroll
    for (int d = 16; d; d >>= 1) m = fmaxf(m, __shfl_xor_sync(0xffffffffu, m, d));
    return m;
}

// Read both published maxima, fold 2^-k into e0/e1, track offset.
#define APPLY_SC() do {                                                 \
    float m_ = fmaxf(sm.slot[0], sm.slot[1]);                           \
    int k_ = ((__float_as_int(m_) >> 23) & 0xff) - 127;                 \
    k_ = k_ < -100 ? -100 : (k_ > 120 ? 120 : k_);                      \
    float sf_ = __int_as_float((127 - k_) << 23);                       \
    off += (float)k_ * LN2F;                                            \
    e0_ *= sf_; e1_ *= sf_;                                             \
} while (0)

#define PUBLISH(V) do {                                                 \
    float mm_ = warp_fmax(fmaxf(__low2float(V), __high2float(V)));      \
    if (l == 0) sm.slot[w] = mm_;                                       \
} while (0)

// Forward step: mv(read RD) -> pair-combine -> *exp(score)[*scale] -> store WR -> bar
#define FS(RD, WR, BUF, AP, PB) do {                                    \
    bf2 zp_ = mvh(RD, Er);                                              \
    zp_ = __hadd2(zp_, u2b(__shfl_xor_sync(0xffffffffu, b2u(zp_), 1))); \
    float2 sv_ = BUF; BUF = *pre; pre += 32;                            \
    float e0_ = __expf(sv_.x), e1_ = __expf(sv_.y);                     \
    if (AP) APPLY_SC();                                                 \
    av = __hmul2(zp_, __floats2bfloat162_rn(e0_, e1_));                 \
    if (PB) PUBLISH(av);                                                \
    store_dup(WR, av);                                                  \
    __syncthreads();                                                    \
} while (0)

// Backward step: w = av*exp(score)[*scale] -> store WR -> bar -> mv(read RD) -> combine
#define BS(RD, WR, BUF, AP, PB) do {                                    \
    float2 sv_ = BUF; BUF = *pre; pre -= 32;                            \
    float e0_ = __expf(sv_.x), e1_ = __expf(sv_.y);                     \
    if (AP) APPLY_SC();                                                 \
    bf2 wv_ = __hmul2(av, __floats2bfloat162_rn(e0_, e1_));             \
    if (PB) PUBLISH(wv_);                                               \
    store_dup(WR, wv_);                                                 \
    __syncthreads();                                                    \
    bf2 zp_ = mvh(RD, Er);                                              \
    av = __hadd2(zp_, u2b(__shfl_xor_sync(0xffffffffu, b2u(zp_), 1)));  \
} while (0)

// Blocks [0,512): one half-chain per 64-thread block, 2-warp split (1024 chain warps).
// Blocks [512,640): gold path, 2 warps/block, one batch per warp.
// Last block to finish computes the final loss.
__global__ void __launch_bounds__(64)
crf_fused(const float* __restrict__ scores, const int* __restrict__ states,
          const float* __restrict__ trans, const float* __restrict__ source,
          const float* __restrict__ sink, float* __restrict__ out)
{
    __shared__ ChainSmem sm;
    const int w = threadIdx.x >> 5;
    const int l = threadIdx.x & 31;

    if (blockIdx.x >= 512) {
        // ---------------- gold path (one warp per batch) ----------------
        const int b = (blockIdx.x - 512) * 2 + w;
        const int* st = states + b * NS;
        const float* sc = scores + (size_t)b * NS * NK;
        float acc = 0.f;
        #pragma unroll 4
        for (int t = l; t < NS; t += 32) {
            int s = st[t];
            float e = sc[t * NK + s];
            float tr = (t + 1 < NS) ? trans[s * NK + st[t + 1]] : 0.f;
            acc += e + tr;
        }
        #pragma unroll
        for (int d = 16; d; d >>= 1) acc += __shfl_xor_sync(0xffffffffu, acc, d);
        if (l == 0) g_gold[b] = acc + source[st[0]] + sink[st[NS - 1]];
    } else {
        // ---------------- one half-chain, 2-warp split ----------------
        const int b = blockIdx.x >> 1;
        const bool fwd = (blockIdx.x & 1) == 0;
        const int jp = 16 * w + (l >> 1);   // output pair this lane produces
        const int h  = l & 1;               // input half this lane sums

        // Read/write pointers: even lanes use copy A [0,32), odd copy B [32,64).
        const uint4* rd0 = h ? (const uint4*)&sm.sB[0][32] : (const uint4*)&sm.sA[0][0];
        const uint4* rd1 = h ? (const uint4*)&sm.sB[1][32] : (const uint4*)&sm.sA[1][0];
        uint2* wr0 = (uint2*)(h ? &sm.sB[0][2 * jp] : &sm.sA[0][2 * jp]);
        uint2* wr1 = (uint2*)(h ? &sm.sB[1][2 * jp] : &sm.sA[1][2 * jp]);

        // Er: 32 bf16x2 = this lane's quarter of exp(transition).
        unsigned Er[32];
        if (fwd) {
            // fwd: Er[i2] = (E[32h+i2][2jp], E[32h+i2][2jp+1])
            #pragma unroll
            for (int i2 = 0; i2 < 32; i2++) {
                float2 tv = ((const float2*)(trans + (32 * h + i2) * NK))[jp];
                Er[i2] = b2u(__floats2bfloat162_rn(expf(tv.x), expf(tv.y)));
            }
        } else {
            // bwd: Er[j2] = (E[2jp][32h+j2], E[2jp+1][32h+j2])
            #pragma unroll
            for (int j2 = 0; j2 < 32; j2++) {
                int col = 32 * h + j2;
                Er[j2] = b2u(__floats2bfloat162_rn(expf(trans[(2 * jp) * NK + col]),
                                                   expf(trans[(2 * jp + 1) * NK + col])));
            }
        }

        const float2* pre0 = (const float2*)(scores + (size_t)b * NS * NK) + jp;
        float off = 0.f;
        bf2 av;

        if (fwd) {
            // alpha_0 = exp(source + scores[b,0,:])
            float2 s0 = pre0[0];
            float2 sr = ((const float2*)source)[jp];
            av = __floats2bfloat162_rn(expf(sr.x + s0.x), expf(sr.y + s0.y));
            store_dup(wr0, av);
            PUBLISH(av);
            __syncthreads();

            // depth-8 prefetch ring: rows 1..8, pre -> row 9
            float2 f0 = pre0[1 * 32], f1 = pre0[2 * 32], f2 = pre0[3 * 32], f3 = pre0[4 * 32];
            float2 f4 = pre0[5 * 32], f5 = pre0[6 * 32], f6 = pre0[7 * 32], f7 = pre0[8 * 32];
            const float2* pre = pre0 + 9 * 32;

            // t = 1..1016: 127 groups of 8 (apply scale at pos 0/4, publish at 3/7)
            #pragma unroll 1
            for (int grp = 0; grp < 127; grp++) {
                FS(rd0, wr1, f0, 1, 0); FS(rd1, wr0, f1, 0, 0);
                FS(rd0, wr1, f2, 0, 0); FS(rd1, wr0, f3, 0, 1);
                FS(rd0, wr1, f4, 1, 0); FS(rd1, wr0, f5, 0, 0);
                FS(rd0, wr1, f6, 0, 0); FS(rd1, wr0, f7, 0, 1);
            }
            // tail t = 1017..1023 (prefetch reads <= row 1031, in bounds)
            FS(rd0, wr1, f0, 1, 0); FS(rd1, wr0, f1, 0, 0);
            FS(rd0, wr1, f2, 0, 0); FS(rd1, wr0, f3, 0, 1);
            FS(rd0, wr1, f4, 1, 0); FS(rd1, wr0, f5, 0, 0);
            FS(rd0, wr1, f6, 0, 0);

            // final block-wide peg + write
            float mw = warp_fmax(fmaxf(__low2float(av), __high2float(av)));
            if (l == 0) sm.slot[w] = mw;
            __syncthreads();
            {
                float m_ = fmaxf(sm.slot[0], sm.slot[1]);
                int k_ = ((__float_as_int(m_) >> 23) & 0xff) - 127;
                k_ = k_ < -100 ? -100 : (k_ > 120 ? 120 : k_);
                float sf_ = __int_as_float((127 - k_) << 23);
                off += (float)k_ * LN2F;
                if (h == 0) {
                    g_vecA[b][2 * jp]     = __low2float(av) * sf_;
                    g_vecA[b][2 * jp + 1] = __high2float(av) * sf_;
                }
                if (threadIdx.x == 0) g_offA[b] = off;
            }
        } else {
            // beta seed = exp(sink); 1024 steps over rows 2047..1024
            float2 sk = ((const float2*)sink)[jp];
            av = __floats2bfloat162_rn(expf(sk.x), expf(sk.y));
            PUBLISH(av);
            __syncthreads();

            // depth-8 prefetch ring: rows 2047..2040, pre -> row 2039
            float2 f0 = pre0[2047 * 32], f1 = pre0[2046 * 32], f2 = pre0[2045 * 32], f3 = pre0[2044 * 32];
            float2 f4 = pre0[2043 * 32], f5 = pre0[2042 * 32], f6 = pre0[2041 * 32], f7 = pre0[2040 * 32];
            const float2* pre = pre0 + 2039 * 32;

            // 128 groups of 8 (prefetch reads >= row 1016, in bounds)
            #pragma unroll 1
            for (int grp = 0; grp < 128; grp++) {
                BS(rd0, wr0, f0, 1, 0); BS(rd1, wr1, f1, 0, 0);
                BS(rd0, wr0, f2, 0, 0); BS(rd1, wr1, f3, 0, 1);
                BS(rd0, wr0, f4, 1, 0); BS(rd1, wr1, f5, 0, 0);
                BS(rd0, wr0, f6, 0, 0); BS(rd1, wr1, f7, 0, 1);
            }

            // final block-wide peg + write
            float mw = warp_fmax(fmaxf(__low2float(av), __high2float(av)));
            if (l == 0) sm.slot[w] = mw;
            __syncthreads();
            {
                float m_ = fmaxf(sm.slot[0], sm.slot[1]);
                int k_ = ((__float_as_int(m_) >> 23) & 0xff) - 127;
                k_ = k_ < -100 ? -100 : (k_ > 120 ? 120 : k_);
                float sf_ = __int_as_float((127 - k_) << 23);
                off += (float)k_ * LN2F;
                if (h == 0) {
                    g_vecB[b][2 * jp]     = __low2float(av) * sf_;
                    g_vecB[b][2 * jp + 1] = __high2float(av) * sf_;
                }
                if (threadIdx.x == 0) g_offB[b] = off;
            }
        }
    }

    // ---------------- completion: last block reduces ----------------
    __syncthreads();
    if (threadIdx.x == 0) {
        __threadfence();
        sm.last = (atomicAdd(&g_done, 1u) == NBLK - 1u) ? 1 : 0;
    }
    __syncthreads();
    if (!sm.last) return;
    __threadfence();

    float part = 0.f;
    for (int rb = threadIdx.x; rb < NB; rb += 64) {
        float s = 0.f;
        #pragma unroll
        for (int j = 0; j < NK; j++) s += g_vecA[rb][j] * g_vecB[rb][j];
        part += logf(s) + g_offA[rb] + g_offB[rb] - g_gold[rb];
    }
    #pragma unroll
    for (int d = 16; d; d >>= 1) part += __shfl_xor_sync(0xffffffffu, part, d);
    if (l == 0) sm.red[w] = part;
    __syncthreads();
    if (threadIdx.x == 0) {
        out[0] = (sm.red[0] + sm.red[1]) * (1.0f / NB);
        g_done = 0;
    }
}

extern "C" void kernel_launch(void* const* d_in, const int* in_sizes, int n_in,
                              void* d_out, int out_size)
{
    const float* scores = (const float*)d_in[0];
    const int*   states = (const int*)d_in[1];
    const float* trans  = (const float*)d_in[2];
    const float* source = (const float*)d_in[3];
    const float* sink   = (const float*)d_in[4];

    crf_fused<<<NBLK, 64>>>(scores, states, trans, source, sink, (float*)d_out);
}

// round 8
// speedup vs baseline: 1.1315x; 1.1315x over previous
#include <cuda_runtime.h>
#include <cuda_bf16.h>
#include <cstdint>

#define NB 256
#define NS 2048
#define NK 64
#define LN2F 0.69314718055994531f
#define NBLK 768

// Scratch (device globals — no allocation allowed)
__device__ float g_vecA[NB][NK];
__device__ float g_vecB[NB][NK];
__device__ float g_offA[NB];
__device__ float g_offB[NB];
__device__ float g_gold[NB];
__device__ unsigned g_done;   // zero-init; reset by last block each launch

typedef __nv_bfloat162 bf2;

__device__ __forceinline__ bf2 u2b(unsigned u) { return *reinterpret_cast<bf2*>(&u); }
__device__ __forceinline__ unsigned b2u(bf2 v) { return *reinterpret_cast<unsigned*>(&v); }

// matvec via warp shfl broadcast (no smem, no sync):
// lane i holds packed (a_2i, a_2i+1); lane l produces z[2l] (zl) and z[2l+1] (zh).
// Ee[i2] pairs E[2i2][2l], E[2i2+1][2l]; Eo same for column 2l+1.
// 32 SHFL.IDX + 64 HFMA2 (4 accumulator chains), fp32 final fold.
__device__ __forceinline__ void mv_shfl(unsigned a_u, const unsigned (&Ee)[32],
                                        const unsigned (&Eo)[32], float& zl, float& zh) {
    bf2 zz = __floats2bfloat162_rn(0.f, 0.f);
    bf2 c0 = zz, c1 = zz, c2 = zz, c3 = zz;
    #pragma unroll
    for (int i = 0; i < 32; i += 2) {
        unsigned v0 = __shfl_sync(0xffffffffu, a_u, i);
        unsigned v1 = __shfl_sync(0xffffffffu, a_u, i + 1);
        c0 = __hfma2(u2b(v0), u2b(Ee[i]), c0);
        c1 = __hfma2(u2b(v0), u2b(Eo[i]), c1);
        c2 = __hfma2(u2b(v1), u2b(Ee[i + 1]), c2);
        c3 = __hfma2(u2b(v1), u2b(Eo[i + 1]), c3);
    }
    bf2 ze = __hadd2(c0, c2), zo = __hadd2(c1, c3);
    zl = __low2float(ze) + __high2float(ze);   // even-i + odd-i partials
    zh = __low2float(zo) + __high2float(zo);
}

__device__ __forceinline__ float warp_fmax(float m) {
    #pragma unroll
    for (int d = 16; d; d >>= 1) m = fmaxf(m, __shfl_xor_sync(0xffffffffu, m, d));
    return m;
}

// Publish (start 5-shfl max chain; consumed >= 1 full step later).
#define PUBLISH() do { mred = warp_fmax(fmaxf(al, ah)); } while (0)
#define PUBLISH_W() do { mred = warp_fmax(fmaxf(wl, wh)); } while (0)

// Apply pending exact power-of-two scale by folding into the exp factors.
#define APPLY() do {                                                   \
    int k_ = ((__float_as_int(mred) >> 23) & 0xff) - 127;              \
    k_ = k_ < -100 ? -100 : (k_ > 120 ? 120 : k_);                     \
    float sf_ = __int_as_float((127 - k_) << 23);                      \
    off += (float)k_ * LN2F;                                           \
    e0 *= sf_; e1 *= sf_;                                              \
} while (0)

// Forward step: shfl-matvec(alpha) -> *exp(score)[*scale]
#define FS(BUF, AP, PB) do {                                           \
    unsigned au_ = b2u(__floats2bfloat162_rn(al, ah));                 \
    float zl_, zh_; mv_shfl(au_, Ee, Eo, zl_, zh_);                    \
    float2 sv_ = BUF; BUF = *pre; pre += 32;                           \
    float e0 = __expf(sv_.x), e1 = __expf(sv_.y);                      \
    if (AP) APPLY();                                                   \
    al = zl_ * e0; ah = zh_ * e1;                                      \
    if (PB) PUBLISH();                                                 \
} while (0)

// Backward step: w = beta*exp(score)[*scale] -> shfl-matvec(w)
#define BS(BUF, AP, PB) do {                                           \
    float2 sv_ = BUF; BUF = *pre; pre -= 32;                           \
    float e0 = __expf(sv_.x), e1 = __expf(sv_.y);                      \
    if (AP) APPLY();                                                   \
    float wl = al * e0, wh = ah * e1;                                  \
    if (PB) PUBLISH_W();                                               \
    unsigned wu_ = b2u(__floats2bfloat162_rn(wl, wh));                 \
    mv_shfl(wu_, Ee, Eo, al, ah);                                      \
} while (0)

// Blocks [0,512): one half-chain per 32-thread block (1 warp), spread chip-wide.
// Blocks [512,768): gold path, one batch per 32-thread block.
// Last block to finish computes the final loss.
__global__ void __launch_bounds__(32)
crf_fused(const float* __restrict__ scores, const int* __restrict__ states,
          const float* __restrict__ trans, const float* __restrict__ source,
          const float* __restrict__ sink, float* __restrict__ out)
{
    const int l = threadIdx.x;   // lane

    if (blockIdx.x >= 512) {
        // ---------------- gold path (one warp per batch) ----------------
        const int b = blockIdx.x - 512;
        const int* st = states + b * NS;
        const float* sc = scores + (size_t)b * NS * NK;
        float acc = 0.f;
        #pragma unroll 4
        for (int t = l; t < NS; t += 32) {
            int s = st[t];
            float e = sc[t * NK + s];
            float tr = (t + 1 < NS) ? trans[s * NK + st[t + 1]] : 0.f;
            acc += e + tr;
        }
        #pragma unroll
        for (int d = 16; d; d >>= 1) acc += __shfl_xor_sync(0xffffffffu, acc, d);
        if (l == 0) g_gold[b] = acc + source[st[0]] + sink[st[NS - 1]];
    } else {
        // ---------------- one half-chain, single warp, no smem ----------------
        const int b = blockIdx.x >> 1;
        const bool fwd = (blockIdx.x & 1) == 0;

        // E banks: Ee -> output column 2l, Eo -> output column 2l+1.
        unsigned Ee[32], Eo[32];
        if (fwd) {
            // z[j] = sum_i a[i] E[i][j]; pack i-pairs.
            #pragma unroll
            for (int i2 = 0; i2 < 32; i2++) {
                const float* r0 = trans + (2 * i2) * NK;
                const float* r1 = trans + (2 * i2 + 1) * NK;
                Ee[i2] = b2u(__floats2bfloat162_rn(expf(r0[2 * l]),     expf(r1[2 * l])));
                Eo[i2] = b2u(__floats2bfloat162_rn(expf(r0[2 * l + 1]), expf(r1[2 * l + 1])));
            }
        } else {
            // beta'[i] = sum_j E[i][j] w[j]; pack j-pairs from rows 2l, 2l+1.
            #pragma unroll
            for (int j2 = 0; j2 < 32; j2++) {
                float2 e0v = ((const float2*)(trans + (2 * l) * NK))[j2];
                float2 e1v = ((const float2*)(trans + (2 * l + 1) * NK))[j2];
                Ee[j2] = b2u(__floats2bfloat162_rn(expf(e0v.x), expf(e0v.y)));
                Eo[j2] = b2u(__floats2bfloat162_rn(expf(e1v.x), expf(e1v.y)));
            }
        }

        const float2* pre0 = (const float2*)(scores + (size_t)b * NS * NK) + l;
        float off = 0.f, al, ah, mred;

        if (fwd) {
            // alpha_0 = exp(source + scores[b,0,:])
            float2 s0 = pre0[0];
            float2 sr = ((const float2*)source)[l];
            al = expf(sr.x + s0.x); ah = expf(sr.y + s0.y);
            PUBLISH();

            // depth-8 prefetch ring: rows 1..8, pre -> row 9
            float2 f0 = pre0[1 * 32], f1 = pre0[2 * 32], f2 = pre0[3 * 32], f3 = pre0[4 * 32];
            float2 f4 = pre0[5 * 32], f5 = pre0[6 * 32], f6 = pre0[7 * 32], f7 = pre0[8 * 32];
            const float2* pre = pre0 + 9 * 32;

            // t = 1..1016: 127 groups of 8 (apply at pos 0/4, publish at 3/7)
            #pragma unroll 1
            for (int grp = 0; grp < 127; grp++) {
                FS(f0, 1, 0); FS(f1, 0, 0); FS(f2, 0, 0); FS(f3, 0, 1);
                FS(f4, 1, 0); FS(f5, 0, 0); FS(f6, 0, 0); FS(f7, 0, 1);
            }
            // tail t = 1017..1023 (prefetch reads <= row 1031, in bounds)
            FS(f0, 1, 0); FS(f1, 0, 0); FS(f2, 0, 0); FS(f3, 0, 1);
            FS(f4, 1, 0); FS(f5, 0, 0); FS(f6, 0, 0);

            // final blocking peg + write
            float m = warp_fmax(fmaxf(al, ah));
            int k = ((__float_as_int(m) >> 23) & 0xff) - 127;
            k = k < -100 ? -100 : (k > 120 ? 120 : k);
            float sf = __int_as_float((127 - k) << 23);
            off += (float)k * LN2F;
            g_vecA[b][2 * l]     = al * sf;
            g_vecA[b][2 * l + 1] = ah * sf;
            if (l == 0) g_offA[b] = off;
        } else {
            // beta seed = exp(sink); 1024 steps over rows 2047..1024
            float2 sk = ((const float2*)sink)[l];
            al = expf(sk.x); ah = expf(sk.y);
            PUBLISH();

            // depth-8 prefetch ring: rows 2047..2040, pre -> row 2039
            float2 f0 = pre0[2047 * 32], f1 = pre0[2046 * 32], f2 = pre0[2045 * 32], f3 = pre0[2044 * 32];
            float2 f4 = pre0[2043 * 32], f5 = pre0[2042 * 32], f6 = pre0[2041 * 32], f7 = pre0[2040 * 32];
            const float2* pre = pre0 + 2039 * 32;

            // 128 groups of 8 (prefetch reads >= row 1016, in bounds)
            #pragma unroll 1
            for (int grp = 0; grp < 128; grp++) {
                BS(f0, 1, 0); BS(f1, 0, 0); BS(f2, 0, 0); BS(f3, 0, 1);
                BS(f4, 1, 0); BS(f5, 0, 0); BS(f6, 0, 0); BS(f7, 0, 1);
            }

            // final blocking peg + write
            float m = warp_fmax(fmaxf(al, ah));
            int k = ((__float_as_int(m) >> 23) & 0xff) - 127;
            k = k < -100 ? -100 : (k > 120 ? 120 : k);
            float sf = __int_as_float((127 - k) << 23);
            off += (float)k * LN2F;
            g_vecB[b][2 * l]     = al * sf;
            g_vecB[b][2 * l + 1] = ah * sf;
            if (l == 0) g_offB[b] = off;
        }
    }

    // ---------------- completion: last warp reduces ----------------
    __syncwarp();
    __threadfence();
    unsigned ticket = 0;
    if (l == 0) ticket = atomicAdd(&g_done, 1u);
    ticket = __shfl_sync(0xffffffffu, ticket, 0);
    if (ticket != NBLK - 1u) return;
    __threadfence();

    float part = 0.f;
    for (int rb = l; rb < NB; rb += 32) {
        float s = 0.f;
        #pragma unroll
        for (int j = 0; j < NK; j++) s += g_vecA[rb][j] * g_vecB[rb][j];
        part += logf(s) + g_offA[rb] + g_offB[rb] - g_gold[rb];
    }
    #pragma unroll
    for (int d = 16; d; d >>= 1) part += __shfl_xor_sync(0xffffffffu, part, d);
    if (l == 0) { out[0] = part * (1.0f / NB); g_done = 0; }
}

extern "C" void kernel_launch(void* const* d_in, const int* in_sizes, int n_in,
                              void* d_out, int out_size)
{
    const float* scores = (const float*)d_in[0];
    const int*   states = (const int*)d_in[1];
    const float* trans  = (const float*)d_in[2];
    const float* source = (const float*)d_in[3];
    const float* sink   = (const float*)d_in[4];

    crf_fused<<<NBLK, 32>>>(scores, states, trans, source, sink, (float*)d_out);
}

// round 9
// speedup vs baseline: 1.5729x; 1.3902x over previous
#include <cuda_runtime.h>
#include <cuda_bf16.h>
#include <cstdint>

#define NB 256
#define NS 2048
#define NK 64
#define LN2F 0.69314718055994531f
#define NBLK 148
#define NWCH 1024   // chain warps (4 per batch)
#define NWGOLD 160  // gold warp slots

// Scratch (device globals — no allocation allowed)
__device__ float g_vecA[NB][NK];   // A_683 (true forward at split 1)
__device__ float g_vecF[NB][NK];   // f = 1^T M2
__device__ float g_vecG[NB][NK];   // g = M2 1
__device__ float g_vecB[NB][NK];   // beta_1366 (true backward at split 2)
__device__ float g_offA[NB];
__device__ float g_offG[NB];
__device__ float g_offB2[NB];
__device__ float g_gold[NB];
__device__ unsigned g_done;        // zero-init; reset by last block each launch

typedef __nv_bfloat162 bf2;

__device__ __forceinline__ bf2 u2b(unsigned u) { return *reinterpret_cast<bf2*>(&u); }
__device__ __forceinline__ unsigned b2u(bf2 v) { return *reinterpret_cast<unsigned*>(&v); }

// matvec: z[2l..2l+1] = sum_i a[i] * E[i][2l..2l+1]
// 16x LDS.128 (broadcast, conflict-free) + 64x HFMA2 (rt 2), 4 acc chains.
__device__ __forceinline__ bf2 mv(const bf2* __restrict__ s, const unsigned (&Er)[NK]) {
    const uint4* q = (const uint4*)s;
    bf2 c0 = __floats2bfloat162_rn(0.f, 0.f);
    bf2 c1 = c0, c2 = c0, c3 = c0;
    #pragma unroll
    for (int g = 0; g < 16; g++) {
        uint4 v = q[g];
        c0 = __hfma2(u2b(v.x), u2b(Er[4 * g + 0]), c0);
        c1 = __hfma2(u2b(v.y), u2b(Er[4 * g + 1]), c1);
        c2 = __hfma2(u2b(v.z), u2b(Er[4 * g + 2]), c2);
        c3 = __hfma2(u2b(v.w), u2b(Er[4 * g + 3]), c3);
    }
    return __hadd2(__hadd2(c0, c1), __hadd2(c2, c3));
}

// Store (v.lo,v.lo),(v.hi,v.hi) dup-pairs as one STS.64 (2 PRMT + 1 STS).
__device__ __forceinline__ void store_dup(bf2* dst, bf2 v) {
    unsigned u = b2u(v);
    uint2 d;
    d.x = __byte_perm(u, u, 0x1010);
    d.y = __byte_perm(u, u, 0x3232);
    *reinterpret_cast<uint2*>(dst) = d;
}

// Exact power-of-two rescale (warp max via 5 shfl), offset in log domain.
__device__ __forceinline__ void rescale(bf2& v, float& off) {
    bf2 m2 = v;
    #pragma unroll
    for (int d = 16; d; d >>= 1)
        m2 = __hmax2(m2, u2b(__shfl_xor_sync(0xffffffffu, b2u(m2), d)));
    float m = fmaxf(__low2float(m2), __high2float(m2));
    int k = (__float_as_int(m) >> 23) - 127;
    k = k < -120 ? -120 : (k > 120 ? 120 : k);
    float scl = __int_as_float((127 - k) << 23);   // 2^-k (exact in bf16)
    v = __hmul2(v, __floats2bfloat162_rn(scl, scl));
    off += (float)k * LN2F;
}

// ---- forward step: matvec(read P) -> *exp(score) -> store P^1 ----
#define FSTEP(P, BUF) do {                                              \
    bf2 c_ = mv(myd[P], Er);                                            \
    float2 sv_ = BUF; BUF = *pre; pre += 32;                            \
    bf2 e_ = __floats2bfloat162_rn(__expf(sv_.x), __expf(sv_.y));       \
    av = __hmul2(c_, e_);                                               \
    store_dup(&myd[P ^ 1][2 * l], av);                                  \
    __syncwarp();                                                       \
} while (0)

#define FSTEP_R(P, BUF) do {                                            \
    bf2 c_ = mv(myd[P], Er);                                            \
    float2 sv_ = BUF; BUF = *pre; pre += 32;                            \
    bf2 e_ = __floats2bfloat162_rn(__expf(sv_.x), __expf(sv_.y));       \
    av = __hmul2(c_, e_);                                               \
    rescale(av, off);                                                   \
    store_dup(&myd[P ^ 1][2 * l], av);                                  \
    __syncwarp();                                                       \
} while (0)

// ---- backward step: w = av*exp(score) -> store P -> matvec(read P) ----
#define BSTEP(P, BUF) do {                                              \
    float2 sv_ = BUF; BUF = *pre; pre -= 32;                            \
    bf2 e_ = __floats2bfloat162_rn(__expf(sv_.x), __expf(sv_.y));       \
    bf2 w_ = __hmul2(av, e_);                                           \
    store_dup(&myd[P][2 * l], w_);                                      \
    __syncwarp();                                                       \
    av = mv(myd[P], Er);                                                \
} while (0)

#define BSTEP_R(P, BUF) do {                                            \
    float2 sv_ = BUF; BUF = *pre; pre -= 32;                            \
    bf2 e_ = __floats2bfloat162_rn(__expf(sv_.x), __expf(sv_.y));       \
    bf2 w_ = __hmul2(av, e_);                                           \
    rescale(w_, off);                                                   \
    store_dup(&myd[P][2 * l], w_);                                      \
    __syncwarp();                                                       \
    av = mv(myd[P], Er);                                                \
} while (0)

// 148 blocks x 8 warps = 1184 warp slots, exactly 1 block/SM:
//  gid in [0,1024): chain warps — batch = gid>>2, role = gid&3:
//    role0: A_683   (true fwd,  rows 1..683,    683 steps, track off)
//    role1: f       (fwd ones,  rows 684..1366, 683 steps, off cancels)
//    role2: g       (bwd ones,  rows 1366..684, 683 steps, track off)
//    role3: beta    (true bwd,  rows 2047..1367, 681 steps, track off)
//  gid in [1024,1184): gold-path warps (batches strided by 160).
// Last block to finish computes the final loss.
__global__ void __launch_bounds__(256, 1)
crf_fused(const float* __restrict__ scores, const int* __restrict__ states,
          const float* __restrict__ trans, const float* __restrict__ source,
          const float* __restrict__ sink, float* __restrict__ out)
{
    __shared__ bf2 adup[8][2][NK];   // [warp][double-buffer][dup bf16x2]
    __shared__ float red[256];
    __shared__ int s_last;

    const int w = threadIdx.x >> 5;
    const int l = threadIdx.x & 31;
    const int gid = blockIdx.x * 8 + w;

    if (gid >= NWCH) {
        // ---------------- gold path (1-2 batches per warp) ----------------
        for (int b = gid - NWCH; b < NB; b += NWGOLD) {
            const int* st = states + b * NS;
            const float* sc = scores + (size_t)b * NS * NK;
            float acc = 0.f;
            #pragma unroll 4
            for (int t = l; t < NS; t += 32) {
                int s = st[t];
                float e = sc[t * NK + s];
                float tr = (t + 1 < NS) ? trans[s * NK + st[t + 1]] : 0.f;
                acc += e + tr;
            }
            #pragma unroll
            for (int d = 16; d; d >>= 1) acc += __shfl_xor_sync(0xffffffffu, acc, d);
            if (l == 0) g_gold[b] = acc + source[st[0]] + sink[st[NS - 1]];
        }
    } else {
        // ---------------- one segment-chain per warp ----------------
        const int b = gid >> 2;
        const int role = gid & 3;
        const bool fwd = role < 2;
        bf2 (*myd)[NK] = adup[w];

        // Er: exp(transition) in bf16x2 (column pair for fwd, row pair for bwd).
        unsigned Er[NK];
        if (fwd) {
            #pragma unroll
            for (int i = 0; i < NK; i++) {
                float2 tv = ((const float2*)(trans + i * NK))[l];
                Er[i] = b2u(__floats2bfloat162_rn(expf(tv.x), expf(tv.y)));
            }
        } else {
            #pragma unroll
            for (int j = 0; j < NK; j++) {
                Er[j] = b2u(__floats2bfloat162_rn(expf(trans[(2 * l) * NK + j]),
                                                  expf(trans[(2 * l + 1) * NK + j])));
            }
        }

        const float2* pre0 = (const float2*)(scores + (size_t)b * NS * NK) + l;
        float off = 0.f;
        bf2 av;

        if (fwd) {
            int base;   // first consumed score row
            if (role == 0) {
                // alpha_0 = exp(source + scores[b,0,:])
                float2 s0 = pre0[0];
                float2 sr = ((const float2*)source)[l];
                av = __floats2bfloat162_rn(expf(sr.x + s0.x), expf(sr.y + s0.y));
                base = 1;
            } else {
                av = __floats2bfloat162_rn(1.f, 1.f);   // f starts from ones
                base = 684;
            }
            store_dup(&myd[0][2 * l], av);
            __syncwarp();

            // depth-8 prefetch ring
            float2 f0 = pre0[(base + 0) * 32], f1 = pre0[(base + 1) * 32];
            float2 f2 = pre0[(base + 2) * 32], f3 = pre0[(base + 3) * 32];
            float2 f4 = pre0[(base + 4) * 32], f5 = pre0[(base + 5) * 32];
            float2 f6 = pre0[(base + 6) * 32], f7 = pre0[(base + 7) * 32];
            const float2* pre = pre0 + (base + 8) * 32;

            // 85 groups of 8 + 3 tail = 683 steps (prefetch <= base+690, in bounds)
            #pragma unroll 1
            for (int grp = 0; grp < 85; grp++) {
                FSTEP(0, f0); FSTEP(1, f1); FSTEP(0, f2); FSTEP(1, f3);
                FSTEP(0, f4); FSTEP(1, f5); FSTEP(0, f6); FSTEP_R(1, f7);
            }
            FSTEP(0, f0); FSTEP(1, f1); FSTEP(0, f2);

            rescale(av, off);   // final peg
            float* dst = (role == 0) ? g_vecA[b] : g_vecF[b];
            dst[2 * l]     = __low2float(av);
            dst[2 * l + 1] = __high2float(av);
            if (l == 0 && role == 0) g_offA[b] = off;   // f's offset cancels
        } else {
            int base;   // first consumed score row (descending)
            if (role == 2) {
                av = __floats2bfloat162_rn(1.f, 1.f);   // g starts from ones
                base = 1366;
            } else {
                float2 sk = ((const float2*)sink)[l];
                av = __floats2bfloat162_rn(expf(sk.x), expf(sk.y));
                base = 2047;
            }

            // depth-8 prefetch ring (descending)
            float2 f0 = pre0[(base - 0) * 32], f1 = pre0[(base - 1) * 32];
            float2 f2 = pre0[(base - 2) * 32], f3 = pre0[(base - 3) * 32];
            float2 f4 = pre0[(base - 4) * 32], f5 = pre0[(base - 5) * 32];
            float2 f6 = pre0[(base - 6) * 32], f7 = pre0[(base - 7) * 32];
            const float2* pre = pre0 + (base - 8) * 32;

            // 85 groups of 8, then 3 tail (role2, 683 steps) or 1 tail (role3, 681).
            // Prefetch stays >= base-690 >= 676, in bounds.
            #pragma unroll 1
            for (int grp = 0; grp < 85; grp++) {
                BSTEP(0, f0); BSTEP(1, f1); BSTEP(0, f2); BSTEP(1, f3);
                BSTEP(0, f4); BSTEP(1, f5); BSTEP(0, f6); BSTEP_R(1, f7);
            }
            BSTEP(0, f0);
            if (role == 2) { BSTEP(1, f1); BSTEP(0, f2); }

            rescale(av, off);   // final peg
            float* dst = (role == 2) ? g_vecG[b] : g_vecB[b];
            dst[2 * l]     = __low2float(av);
            dst[2 * l + 1] = __high2float(av);
            if (l == 0) {
                if (role == 2) g_offG[b] = off; else g_offB2[b] = off;
            }
        }
    }

    // ---------------- completion: last block reduces ----------------
    __syncthreads();
    if (threadIdx.x == 0) {
        __threadfence();
        s_last = (atomicAdd(&g_done, 1u) == NBLK - 1u) ? 1 : 0;
    }
    __syncthreads();
    if (!s_last) return;
    __threadfence();

    // loss_b = log(A.g) + log(f.beta) - log(f.1) + offA + offG + offB - gold
    const int b = threadIdx.x;   // one batch per thread (256 threads)
    float dAG = 0.f, dFB = 0.f, dF1 = 0.f;
    #pragma unroll 4
    for (int j = 0; j < NK; j++) {
        float fj = g_vecF[b][j];
        dAG += g_vecA[b][j] * g_vecG[b][j];
        dFB += fj * g_vecB[b][j];
        dF1 += fj;
    }
    float loss = logf(dAG) + logf(dFB) - logf(dF1)
               + g_offA[b] + g_offG[b] + g_offB2[b] - g_gold[b];

    red[b] = loss;
    __syncthreads();
    #pragma unroll
    for (int k = 128; k; k >>= 1) {
        if (b < k) red[b] += red[b + k];
        __syncthreads();
    }
    if (b == 0) { out[0] = red[0] * (1.0f / NB); g_done = 0; }
}

extern "C" void kernel_launch(void* const* d_in, const int* in_sizes, int n_in,
                              void* d_out, int out_size)
{
    const float* scores = (const float*)d_in[0];
    const int*   states = (const int*)d_in[1];
    const float* trans  = (const float*)d_in[2];
    const float* source = (const float*)d_in[3];
    const float* sink   = (const float*)d_in[4];

    crf_fused<<<NBLK, 256>>>(scores, states, trans, source, sink, (float*)d_out);
}